// round 11
// baseline (speedup 1.0000x reference)
#include <cuda_runtime.h>
#include <cuda_bf16.h>

#define NB 64
#define NT 512
#define EMBED 1024
#define WIN 64
#define NK (2*WIN+1)   // 129
#define GW 256         // matrix W dimension
#define NPROD 32       // producer blocks in phase C
#define NKMAX 5        // max keys per producer (block 31 takes 5)

// Scratch (device globals: no allocation allowed)
__device__ float g_wpart[NB][EMBED];     // per-block partial w vectors
__device__ float g_ypart[NPROD][EMBED];
__device__ float g_zpart[NPROD];
__device__ float g_o[EMBED];
// Grid barrier: EXACT style that has passed 5/5 (atomic arrive + atomic poll + nanosleep).
__device__ unsigned g_arrive = 0;
__device__ unsigned g_rel = 0;

__device__ __forceinline__ void grid_sync() {
    __threadfence();
    __syncthreads();
    if (threadIdx.x == 0) {
        unsigned a = atomicAdd(&g_arrive, 1u) + 1u;
        unsigned target = (a + NB - 1u) / NB;
        if ((a % NB) == 0u) {
            atomicAdd(&g_rel, 1u);
        } else {
            while (atomicAdd(&g_rel, 0u) < target) { __nanosleep(32); }
        }
    }
    __syncthreads();
}

__device__ __forceinline__ float warp_reduce(float v) {
    #pragma unroll
    for (int o = 16; o; o >>= 1) v += __shfl_xor_sync(0xffffffffu, v, o);
    return v;
}

__device__ __forceinline__ float dot4(float4 a, float4 b) {
    return a.x * b.x + a.y * b.y + a.z * b.z + a.w * b.w;
}

__device__ __forceinline__ void cp_async16(unsigned smem_addr, const void* gptr) {
    asm volatile("cp.async.cg.shared.global [%0], [%1], 16;"
                 :: "r"(smem_addr), "l"(gptr));
}

// Dynamic smem layout (floats):
//  xs    [0,1024)        x / abar / o staging (256 float4)
//  wacc  [1024,2048)     w-partial combine (256 float4)
//  misc  [2048,2080)     q broadcast / warp accs / zinv / p_k
//  dotp  [2080,2208)     16 warps x 8 slots
//  WvS   [2208,18592)    16 Wv rows (64KB)
//  WoS   [18592,34976)   16 Wo rows (64KB)
#define SM_FLOATS 34976
#define SM_BYTES  (SM_FLOATS * 4)

__global__ void __launch_bounds__(NT, 1)
fused_local_attn(const float* __restrict__ matrix,
                 const float* __restrict__ Wq, const float* __restrict__ bq,
                 const float* __restrict__ Wk,
                 const float* __restrict__ Wv, const float* __restrict__ bv,
                 const float* __restrict__ Wo, const float* __restrict__ bo,
                 const int* __restrict__ ppx, const int* __restrict__ ppy,
                 float* __restrict__ out)
{
    const int tid  = threadIdx.x;
    const int bid  = blockIdx.x;
    const int wid  = tid >> 5;
    const int lane = tid & 31;

    extern __shared__ __align__(16) float sm[];
    float4* xs_4   = (float4*)sm;               // 256 float4
    float4* wacc_4 = (float4*)(sm + 1024);      // 256 float4
    float*  misc   = sm + 2048;                 // 32
    float*  dotp   = sm + 2080;                 // 128
    float4* WvS_4  = (float4*)(sm + 2208);      // 4096 float4
    float4* WoS_4  = (float4*)(sm + 18592);     // 4096 float4

    // ---- cp.async prefetch of this block's Wv and Wo rows (overlaps all) --
    {
        unsigned wv_s = (unsigned)__cvta_generic_to_shared(WvS_4);
        unsigned wo_s = (unsigned)__cvta_generic_to_shared(WoS_4);
        const float4* vsrc = (const float4*)Wv + (size_t)bid * 4096;
        const float4* osrc = (const float4*)Wo + (size_t)bid * 4096;
        #pragma unroll
        for (int j = 0; j < 8; j++)
            cp_async16(wv_s + (unsigned)(tid + j * 512) * 16u, vsrc + tid + j * 512);
        asm volatile("cp.async.commit_group;");
        #pragma unroll
        for (int j = 0; j < 8; j++)
            cp_async16(wo_s + (unsigned)(tid + j * 512) * 16u, osrc + tid + j * 512);
        asm volatile("cp.async.commit_group;");
    }

    const int px = ppx[0], py = ppy[0];
    const float* rowbase = matrix + (size_t)(2 * px - WIN) * GW * EMBED;
    const float4* xvec4 = (const float4*)(rowbase + (size_t)(2 * py - WIN) * EMBED);
    const float4* keys4 = (const float4*)(rowbase + (size_t)(py - WIN) * EMBED);

    // ===== Phase AB: q rows -> local Wk partial (NO grid sync between) ====
    {
        if (tid < 256) xs_4[tid] = xvec4[tid];
        __syncthreads();
        // q for this block's 16 rows (1 warp/row)
        int row = bid * 16 + wid;
        const float4* Wrow = (const float4*)(Wq + (size_t)row * EMBED);
        float acc = 0.f;
        #pragma unroll
        for (int i = 0; i < 8; i++)
            acc += dot4(Wrow[i * 32 + lane], xs_4[i * 32 + lane]);
        acc = warp_reduce(acc);
        if (lane == 0) misc[wid] = acc + bq[row];
        __syncthreads();
        // partial w: two warp-groups over f, 8 warps span e (256 float4)
        const int grp = wid >> 3, wsub = wid & 7;
        const int ei = wsub * 32 + lane;          // e-float4 index 0..255
        float4 facc = make_float4(0.f, 0.f, 0.f, 0.f);
        #pragma unroll
        for (int j = 0; j < 8; j++) {
            int f = grp * 8 + j;
            float qf = misc[f];
            float4 kw = ((const float4*)Wk)[(size_t)(bid * 16 + f) * 256 + ei];
            facc.x += qf * kw.x; facc.y += qf * kw.y;
            facc.z += qf * kw.z; facc.w += qf * kw.w;
        }
        if (grp == 0) wacc_4[ei] = facc;
        __syncthreads();
        if (grp == 1) {
            float4 t4 = wacc_4[ei];
            t4.x += facc.x; t4.y += facc.y; t4.z += facc.z; t4.w += facc.w;
            ((float4*)g_wpart[bid])[ei] = t4;
        }
    }
    grid_sync();   // #1

    // ===== Phase C (producers bid<NPROD): w reduce, s_k, p_k, y, z ========
    if (bid < NPROD) {
        const int kbase = bid * 4;
        const int nk = (bid == NPROD - 1) ? 5 : 4;   // block 31: k=124..128
        float4 w4 = make_float4(0.f, 0.f, 0.f, 0.f);
        float4 kv[NKMAX];
        #pragma unroll
        for (int j = 0; j < NKMAX; j++) kv[j] = make_float4(0.f, 0.f, 0.f, 0.f);
        if (tid < 256) {
            #pragma unroll 8
            for (int p = 0; p < NB; p++) {
                float4 t4 = __ldcg(&((const float4*)g_wpart[p])[tid]);
                w4.x += t4.x; w4.y += t4.y; w4.z += t4.z; w4.w += t4.w;
            }
            #pragma unroll
            for (int j = 0; j < NKMAX; j++)
                if (j < nk) kv[j] = keys4[(size_t)(kbase + j) * 256 + tid];
        }
        #pragma unroll
        for (int j = 0; j < NKMAX; j++) {
            float p = (j < nk) ? dot4(w4, kv[j]) : 0.f;
            p = warp_reduce(p);
            if (lane == 0) dotp[wid * 8 + j] = p;
        }
        __syncthreads();
        if (tid < NKMAX) {
            float s = 0.f;
            #pragma unroll
            for (int w = 0; w < 8; w++) s += dotp[w * 8 + tid];   // warps 0-7 hold tid<256
            misc[20 + tid] = (tid < nk) ? __expf(s * 0.03125f) : 0.f;
        }
        __syncthreads();
        if (tid < 256) {
            float4 y = make_float4(0.f, 0.f, 0.f, 0.f);
            #pragma unroll
            for (int j = 0; j < NKMAX; j++) {
                float pk = misc[20 + j];
                y.x += pk * kv[j].x; y.y += pk * kv[j].y;
                y.z += pk * kv[j].z; y.w += pk * kv[j].w;
            }
            ((float4*)g_ypart[bid])[tid] = y;
        }
        if (tid == 0) {
            float z = 0.f;
            #pragma unroll
            for (int j = 0; j < NKMAX; j++) z += misc[20 + j];
            g_zpart[bid] = z;
        }
    }
    grid_sync();   // #2

    // ===== Phase E: abar from y/z parts, o = Wv @ abar + bv (smem Wv) =====
    asm volatile("cp.async.wait_group 1;");
    __syncthreads();
    {
        if (wid == 0) {
            float z = __ldcg(&g_zpart[lane]);     // NPROD=32 values
            z = warp_reduce(z);
            if (lane == 0) misc[16] = 1.f / z;
        }
        float4 s0 = make_float4(0.f, 0.f, 0.f, 0.f);
        float4 s1 = make_float4(0.f, 0.f, 0.f, 0.f);
        if (tid < 256) {
            #pragma unroll
            for (int p = 0; p < NPROD; p += 2) {
                float4 a0 = __ldcg(&((const float4*)g_ypart[p])[tid]);
                float4 a1 = __ldcg(&((const float4*)g_ypart[p + 1])[tid]);
                s0.x += a0.x; s0.y += a0.y; s0.z += a0.z; s0.w += a0.w;
                s1.x += a1.x; s1.y += a1.y; s1.z += a1.z; s1.w += a1.w;
            }
        }
        __syncthreads();                           // zinv ready
        if (tid < 256) {
            float zinv = misc[16];
            float4 ab;
            ab.x = (s0.x + s1.x) * zinv; ab.y = (s0.y + s1.y) * zinv;
            ab.z = (s0.z + s1.z) * zinv; ab.w = (s0.w + s1.w) * zinv;
            xs_4[tid] = ab;
        }
        __syncthreads();
        float acc = 0.f;
        #pragma unroll
        for (int i = 0; i < 8; i++)
            acc += dot4(WvS_4[wid * 256 + i * 32 + lane], xs_4[i * 32 + lane]);
        acc = warp_reduce(acc);
        if (lane == 0) misc[wid] = acc;
        __syncthreads();
        if (tid < 16) g_o[bid * 16 + tid] = misc[tid] + bv[bid * 16 + tid];
    }
    grid_sync();   // #3

    // ===== Phase F: out = Wo @ o + bo (smem Wo) ===========================
    asm volatile("cp.async.wait_group 0;");
    __syncthreads();
    {
        if (tid < 256) xs_4[tid] = __ldcg(&((const float4*)g_o)[tid]);
        __syncthreads();
        float acc = 0.f;
        #pragma unroll
        for (int i = 0; i < 8; i++)
            acc += dot4(WoS_4[wid * 256 + i * 32 + lane], xs_4[i * 32 + lane]);
        acc = warp_reduce(acc);
        if (lane == 0) misc[wid] = acc;
        __syncthreads();
        if (tid < 16) out[bid * 16 + tid] = misc[tid] + bo[bid * 16 + tid];
    }
}

extern "C" void kernel_launch(void* const* d_in, const int* in_sizes, int n_in,
                              void* d_out, int out_size) {
    const float* matrix = (const float*)d_in[0];
    const float* Wq = (const float*)d_in[1];
    const float* bq = (const float*)d_in[2];
    const float* Wk = (const float*)d_in[3];
    // d_in[4] = bk: eliminated (cancels in softmax ratio)
    const float* Wv = (const float*)d_in[5];
    const float* bv = (const float*)d_in[6];
    const float* Wo = (const float*)d_in[7];
    const float* bo = (const float*)d_in[8];
    const int* px = (const int*)d_in[9];
    const int* py = (const int*)d_in[10];

    cudaFuncSetAttribute(fused_local_attn,
                         cudaFuncAttributeMaxDynamicSharedMemorySize, SM_BYTES);
    fused_local_attn<<<NB, NT, SM_BYTES>>>(matrix, Wq, bq, Wk, Wv, bv, Wo, bo,
                                           px, py, (float*)d_out);
}

// round 13
// speedup vs baseline: 1.0468x; 1.0468x over previous
#include <cuda_runtime.h>
#include <cuda_bf16.h>

#define NB 64
#define NT 512
#define EMBED 1024
#define WIN 64
#define NK (2*WIN+1)   // 129
#define GW 256         // matrix W dimension
#define NPROD 32       // producer blocks in phase C
#define NKMAX 5        // keys per producer slot (block 31 uses all 5)

// Scratch (device globals: no allocation allowed)
__device__ float g_q[EMBED];
__device__ float g_wpart[2][EMBED];
__device__ float g_ypart[NPROD][EMBED];
__device__ float g_zpart[NPROD];
__device__ float g_o[EMBED];
// Grid barrier: EXACT style that has passed 6/6 (atomic arrive + atomic poll + nanosleep).
__device__ unsigned g_arrive = 0;
__device__ unsigned g_rel = 0;

__device__ __forceinline__ void grid_sync() {
    __threadfence();
    __syncthreads();
    if (threadIdx.x == 0) {
        unsigned a = atomicAdd(&g_arrive, 1u) + 1u;
        unsigned target = (a + NB - 1u) / NB;
        if ((a % NB) == 0u) {
            atomicAdd(&g_rel, 1u);
        } else {
            while (atomicAdd(&g_rel, 0u) < target) { __nanosleep(32); }
        }
    }
    __syncthreads();
}

__device__ __forceinline__ float warp_reduce(float v) {
    #pragma unroll
    for (int o = 16; o; o >>= 1) v += __shfl_xor_sync(0xffffffffu, v, o);
    return v;
}

__device__ __forceinline__ float dot4(float4 a, float4 b) {
    return a.x * b.x + a.y * b.y + a.z * b.z + a.w * b.w;
}

__device__ __forceinline__ void cp_async16(unsigned smem_addr, const void* gptr) {
    asm volatile("cp.async.cg.shared.global [%0], [%1], 16;"
                 :: "r"(smem_addr), "l"(gptr));
}

// Dynamic smem layout (floats):
//  xs    [0,1024)       x / abar / o staging (256 float4)
//  R1    [1024,3072)    512 float4 (phase B)
//  sq    [3072,3584)    512 floats (phase B q chunk)
//  R2    [3584,3840)    64 float4
//  dotp  [3840,3968)    16 warps x 8 slots
//  misc  [3968,4000)    warp accs / zinv / p_k
//  keyS  [4000,9120)    5 keys x 1024 (producers)
//  WvS   [9120,25504)   16 Wv rows (64KB)
//  WoS   [25504,41888)  16 Wo rows (64KB)
#define SM_FLOATS 41888
#define SM_BYTES  (SM_FLOATS * 4)

__global__ void __launch_bounds__(NT, 1)
fused_local_attn(const float* __restrict__ matrix,
                 const float* __restrict__ Wq, const float* __restrict__ bq,
                 const float* __restrict__ Wk,
                 const float* __restrict__ Wv, const float* __restrict__ bv,
                 const float* __restrict__ Wo, const float* __restrict__ bo,
                 const int* __restrict__ ppx, const int* __restrict__ ppy,
                 float* __restrict__ out)
{
    const int tid  = threadIdx.x;
    const int bid  = blockIdx.x;
    const int wid  = tid >> 5;
    const int lane = tid & 31;

    extern __shared__ __align__(16) float sm[];
    float4* xs_4   = (float4*)sm;
    float4* R1_4   = (float4*)(sm + 1024);
    float*  sq     = sm + 3072;
    float4* R2_4   = (float4*)(sm + 3584);
    float*  dotp   = sm + 3840;
    float*  misc   = sm + 3968;
    float4* keyS_4 = (float4*)(sm + 4000);
    float4* WvS_4  = (float4*)(sm + 9120);
    float4* WoS_4  = (float4*)(sm + 25504);

    // ---- Top-of-kernel prefetches ---------------------------------------
    // 1) Wv/Wo rows -> smem (px/py independent; issue immediately)
    {
        unsigned wv_s = (unsigned)__cvta_generic_to_shared(WvS_4);
        unsigned wo_s = (unsigned)__cvta_generic_to_shared(WoS_4);
        const float4* vsrc = (const float4*)Wv + (size_t)bid * 4096;
        const float4* osrc = (const float4*)Wo + (size_t)bid * 4096;
        #pragma unroll
        for (int j = 0; j < 8; j++)
            cp_async16(wv_s + (unsigned)(tid + j * 512) * 16u, vsrc + tid + j * 512);
        asm volatile("cp.async.commit_group;");
        #pragma unroll
        for (int j = 0; j < 8; j++)
            cp_async16(wo_s + (unsigned)(tid + j * 512) * 16u, osrc + tid + j * 512);
        asm volatile("cp.async.commit_group;");
    }

    // 2) biases -> registers (off the phase tails)
    float my_bq = 0.f, my_bv = 0.f, my_bo = 0.f;
    if (tid < 16) {
        my_bq = __ldcg(&bq[bid * 16 + tid]);
        my_bv = __ldcg(&bv[bid * 16 + tid]);
        my_bo = __ldcg(&bo[bid * 16 + tid]);
    }

    // 3) px/py, then producers stage their keys via cp.async
    const int px = __ldcg(&ppx[0]), py = __ldcg(&ppy[0]);
    const float* rowbase = matrix + (size_t)(2 * px - WIN) * GW * EMBED;
    const float4* xvec4 = (const float4*)(rowbase + (size_t)(2 * py - WIN) * EMBED);
    const float4* keys4 = (const float4*)(rowbase + (size_t)(py - WIN) * EMBED);

    if (bid < NPROD) {
        unsigned k_s = (unsigned)__cvta_generic_to_shared(keyS_4);
        const float4* ksrc = keys4 + (size_t)(bid * 4) * 256;   // 5 keys = 1280 f4
        #pragma unroll
        for (int j = 0; j < 3; j++) {
            int idx = tid + j * 512;
            if (idx < NKMAX * 256)
                cp_async16(k_s + (unsigned)idx * 16u, ksrc + idx);
        }
        asm volatile("cp.async.commit_group;");
    }

    // =========== Phase A: q = Wq @ x + bq (16 rows/block, 1 warp/row) ====
    {
        if (tid < 256) xs_4[tid] = xvec4[tid];
        __syncthreads();
        int row = bid * 16 + wid;
        const float4* Wrow = (const float4*)(Wq + (size_t)row * EMBED);
        float acc = 0.f;
        #pragma unroll
        for (int i = 0; i < 8; i++)
            acc += dot4(Wrow[i * 32 + lane], xs_4[i * 32 + lane]);
        acc = warp_reduce(acc);
        if (lane == 0) misc[wid] = acc;
        __syncthreads();
        if (tid < 16) g_q[bid * 16 + tid] = misc[tid] + my_bq;
    }
    grid_sync();   // #1

    // ===== Phase B: w-partials. fc=bid>>5 (2 f-chunks of 512), et=bid&31 ==
    {
        const int fc = bid >> 5, et = bid & 31;
        const int f0 = fc * 512;
        if (tid < 128) ((float4*)sq)[tid] = __ldcg(&((const float4*)g_q)[f0 / 4 + tid]);
        __syncthreads();
        const int v = tid & 7, fl = tid >> 3;
        float4 acc = make_float4(0.f, 0.f, 0.f, 0.f);
        #pragma unroll
        for (int i = 0; i < 8; i++) {
            float qf = sq[i * 64 + fl];
            float4 wv = ((const float4*)Wk)[(size_t)(f0 + i * 64 + fl) * 256 + et * 8 + v];
            acc.x += qf * wv.x; acc.y += qf * wv.y; acc.z += qf * wv.z; acc.w += qf * wv.w;
        }
        R1_4[tid] = acc;
        __syncthreads();
        if (tid < 64) {                           // 512 -> 64
            int vv = tid & 7, g = tid >> 3;
            float4 s = make_float4(0.f, 0.f, 0.f, 0.f);
            #pragma unroll
            for (int j = 0; j < 8; j++) {
                float4 t4 = R1_4[vv + 8 * (g * 8 + j)];
                s.x += t4.x; s.y += t4.y; s.z += t4.z; s.w += t4.w;
            }
            R2_4[tid] = s;
        }
        __syncthreads();
        if (tid < 8) {                            // 64 -> 8 float4
            float4 s = make_float4(0.f, 0.f, 0.f, 0.f);
            #pragma unroll
            for (int g = 0; g < 8; g++) {
                float4 t4 = R2_4[tid + 8 * g];
                s.x += t4.x; s.y += t4.y; s.z += t4.z; s.w += t4.w;
            }
            ((float4*)g_wpart[fc])[et * 8 + tid] = s;
        }
    }
    grid_sync();   // #2

    // ===== Phase C (producers): s_k, p_k = exp, y_part, z_part ===========
    if (bid < NPROD) {
        asm volatile("cp.async.wait_group 0;");   // keys (and Wv/Wo) resident
        __syncthreads();
        const int kbase = bid * 4;
        const int nk = (bid == NPROD - 1) ? 5 : 4;
        float4 w4 = make_float4(0.f, 0.f, 0.f, 0.f);
        float4 kv[NKMAX];
        #pragma unroll
        for (int j = 0; j < NKMAX; j++) kv[j] = make_float4(0.f, 0.f, 0.f, 0.f);
        if (tid < 256) {
            float4 a0 = __ldcg(&((const float4*)g_wpart[0])[tid]);
            float4 a1 = __ldcg(&((const float4*)g_wpart[1])[tid]);
            w4.x = a0.x + a1.x; w4.y = a0.y + a1.y;
            w4.z = a0.z + a1.z; w4.w = a0.w + a1.w;
            #pragma unroll
            for (int j = 0; j < NKMAX; j++)
                kv[j] = keyS_4[j * 256 + tid];
        }
        #pragma unroll
        for (int j = 0; j < NKMAX; j++) {
            float p = (j < nk) ? dot4(w4, kv[j]) : 0.f;
            p = warp_reduce(p);
            if (lane == 0) dotp[wid * 8 + j] = p;
        }
        __syncthreads();
        if (tid < NKMAX) {
            float s = 0.f;
            #pragma unroll
            for (int w = 0; w < 8; w++) s += dotp[w * 8 + tid];   // warps 0-7 hold tid<256
            misc[20 + tid] = (tid < nk) ? __expf(s * 0.03125f) : 0.f;
        }
        __syncthreads();
        if (tid < 256) {
            float4 y = make_float4(0.f, 0.f, 0.f, 0.f);
            #pragma unroll
            for (int j = 0; j < NKMAX; j++) {
                float pk = misc[20 + j];
                y.x += pk * kv[j].x; y.y += pk * kv[j].y;
                y.z += pk * kv[j].z; y.w += pk * kv[j].w;
            }
            ((float4*)g_ypart[bid])[tid] = y;
        }
        if (tid == 0) {
            float z = 0.f;
            #pragma unroll
            for (int j = 0; j < NKMAX; j++) z += misc[20 + j];
            g_zpart[bid] = z;
        }
    }
    grid_sync();   // #3

    // ===== Phase E: abar from y/z parts, o = Wv @ abar + bv (smem Wv) ====
    asm volatile("cp.async.wait_group 0;");
    __syncthreads();
    {
        if (wid == 0) {
            float z = __ldcg(&g_zpart[lane]);     // 32 values
            z = warp_reduce(z);
            if (lane == 0) misc[16] = 1.f / z;
        }
        float4 s0 = make_float4(0.f, 0.f, 0.f, 0.f);
        float4 s1 = make_float4(0.f, 0.f, 0.f, 0.f);
        if (tid < 256) {
            #pragma unroll
            for (int p = 0; p < NPROD; p += 2) {
                float4 a0 = __ldcg(&((const float4*)g_ypart[p])[tid]);
                float4 a1 = __ldcg(&((const float4*)g_ypart[p + 1])[tid]);
                s0.x += a0.x; s0.y += a0.y; s0.z += a0.z; s0.w += a0.w;
                s1.x += a1.x; s1.y += a1.y; s1.z += a1.z; s1.w += a1.w;
            }
        }
        __syncthreads();                           // zinv ready
        if (tid < 256) {
            float zinv = misc[16];
            float4 ab;
            ab.x = (s0.x + s1.x) * zinv; ab.y = (s0.y + s1.y) * zinv;
            ab.z = (s0.z + s1.z) * zinv; ab.w = (s0.w + s1.w) * zinv;
            xs_4[tid] = ab;
        }
        __syncthreads();
        float acc = 0.f;
        #pragma unroll
        for (int i = 0; i < 8; i++)
            acc += dot4(WvS_4[wid * 256 + i * 32 + lane], xs_4[i * 32 + lane]);
        acc = warp_reduce(acc);
        if (lane == 0) misc[wid] = acc;
        __syncthreads();
        if (tid < 16) g_o[bid * 16 + tid] = misc[tid] + my_bv;
    }
    grid_sync();   // #4

    // ===== Phase F: out = Wo @ o + bo (smem Wo) ==========================
    {
        if (tid < 256) xs_4[tid] = __ldcg(&((const float4*)g_o)[tid]);
        __syncthreads();
        float acc = 0.f;
        #pragma unroll
        for (int i = 0; i < 8; i++)
            acc += dot4(WoS_4[wid * 256 + i * 32 + lane], xs_4[i * 32 + lane]);
        acc = warp_reduce(acc);
        if (lane == 0) misc[wid] = acc;
        __syncthreads();
        if (tid < 16) out[bid * 16 + tid] = misc[tid] + my_bo;
    }
}

extern "C" void kernel_launch(void* const* d_in, const int* in_sizes, int n_in,
                              void* d_out, int out_size) {
    const float* matrix = (const float*)d_in[0];
    const float* Wq = (const float*)d_in[1];
    const float* bq = (const float*)d_in[2];
    const float* Wk = (const float*)d_in[3];
    // d_in[4] = bk: eliminated (cancels in softmax ratio)
    const float* Wv = (const float*)d_in[5];
    const float* bv = (const float*)d_in[6];
    const float* Wo = (const float*)d_in[7];
    const float* bo = (const float*)d_in[8];
    const int* px = (const int*)d_in[9];
    const int* py = (const int*)d_in[10];

    cudaFuncSetAttribute(fused_local_attn,
                         cudaFuncAttributeMaxDynamicSharedMemorySize, SM_BYTES);
    fused_local_attn<<<NB, NT, SM_BYTES>>>(matrix, Wq, bq, Wk, Wv, bv, Wo, bo,
                                           px, py, (float*)d_out);
}